// round 1
// baseline (speedup 1.0000x reference)
#include <cuda_runtime.h>
#include <math.h>

#define B_   4
#define T_   2048
#define C_   1024
#define NH_  16
#define HD_  64
#define M_   (B_*T_)      // 8192

// Scratch (allocation-free: __device__ globals)
__device__ float g_q[B_*NH_*T_*HD_];
__device__ float g_k[B_*NH_*T_*HD_];
__device__ float g_v[B_*NH_*T_*HD_];
__device__ float g_att[M_*C_];

// ---------------------------------------------------------------------------
// Register-tiled SGEMM: C[M,N] = A[M,K] @ B[K,N] + bias[N]
// BM=128, BN=128, BK=8, 256 threads, 8x8 per-thread microtile.
// QKV=true: scatter epilogue into g_q/g_k/g_v with [B,NH,T,HD] layout.
// QKV=false: A is g_att (param A ignored), dense epilogue to `out`.
// ---------------------------------------------------------------------------
#define BM 128
#define BN 128
#define BK 8
#define TM 8
#define TN 8

template<int N, bool QKV>
__global__ __launch_bounds__(256)
void sgemm_kernel(const float* __restrict__ A,
                  const float* __restrict__ Bm,
                  const float* __restrict__ bias,
                  float* __restrict__ out)
{
    const int K = 1024;
    __shared__ float As[BK][BM];
    __shared__ float Bs[BK][BN];

    const int tid  = threadIdx.x;
    const int cRow = blockIdx.y;
    const int cCol = blockIdx.x;

    const float* Ap = (QKV ? A : (const float*)g_att) + (size_t)cRow * BM * K;
    const float* Bp = Bm + cCol * BN;

    const int irA = tid >> 1;        // 0..127
    const int icA = tid & 1;         // 0..1  (float4 index in row of 8)
    const int irB = tid >> 5;        // 0..7
    const int icB = tid & 31;        // 0..31 (float4 index in row of 128)
    const int tr  = tid >> 4;        // 0..15
    const int tc  = tid & 15;        // 0..15

    float acc[TM][TN];
#pragma unroll
    for (int i = 0; i < TM; i++)
#pragma unroll
        for (int j = 0; j < TN; j++) acc[i][j] = 0.f;

    for (int k0 = 0; k0 < K; k0 += BK) {
        float4 a = *(const float4*)(Ap + irA * K + icA * 4);
        As[icA*4+0][irA] = a.x;
        As[icA*4+1][irA] = a.y;
        As[icA*4+2][irA] = a.z;
        As[icA*4+3][irA] = a.w;
        *(float4*)&Bs[irB][icB*4] = *(const float4*)(Bp + irB * N + icB * 4);
        __syncthreads();
        Ap += BK;
        Bp += (size_t)BK * N;

#pragma unroll
        for (int k = 0; k < BK; k++) {
            float rM[TM], rN[TN];
            *(float4*)&rM[0] = *(const float4*)&As[k][tr*TM];
            *(float4*)&rM[4] = *(const float4*)&As[k][tr*TM + 4];
            *(float4*)&rN[0] = *(const float4*)&Bs[k][tc*TN];
            *(float4*)&rN[4] = *(const float4*)&Bs[k][tc*TN + 4];
#pragma unroll
            for (int i = 0; i < TM; i++)
#pragma unroll
                for (int j = 0; j < TN; j++)
                    acc[i][j] += rM[i] * rN[j];
        }
        __syncthreads();
    }

    // Epilogue
#pragma unroll
    for (int i = 0; i < TM; i++) {
        const int row = cRow * BM + tr * TM + i;       // m index (b*T + t)
        const int bb = row >> 11;                      // / T_
        const int tt = row & (T_ - 1);
#pragma unroll
        for (int j = 0; j < TN; j += 4) {
            const int col = cCol * BN + tc * TN + j;   // n index
            float4 v;
            v.x = acc[i][j+0] + bias[col+0];
            v.y = acc[i][j+1] + bias[col+1];
            v.z = acc[i][j+2] + bias[col+2];
            v.w = acc[i][j+3] + bias[col+3];
            if (QKV) {
                const int which = col >> 10;           // 0:q 1:k 2:v
                const int cc = col & (C_ - 1);
                const int h = cc >> 6;
                const int d = cc & (HD_ - 1);
                float* dst = (which == 0) ? g_q : (which == 1) ? g_k : g_v;
                // [B, NH, T, HD]
                *(float4*)&dst[(((size_t)(bb * NH_ + h)) * T_ + tt) * HD_ + d] = v;
            } else {
                *(float4*)&out[(size_t)row * N + col] = v;
            }
        }
    }
}

// ---------------------------------------------------------------------------
// Flash attention (fp32, online softmax). One block = 64 queries of one head.
// 256 threads, each owns a 4x4 microtile of the 64x64 S and O tiles.
// Causal: only key tiles kt <= qi; diagonal tile masked.
// ---------------------------------------------------------------------------
#define BQ  64
#define BKT 64
#define QKS 68   // Q/K/V smem row stride (16B-aligned, conflict-spread)
#define SST 67   // S smem row stride (odd-ish: distinct banks across rows)

#define FLASH_SMEM ((3*BQ*QKS + BQ*SST + 3*BQ) * (int)sizeof(float))  // 70144 B

__global__ __launch_bounds__(256)
void flash_kernel()
{
    extern __shared__ float sm[];
    float* Qs   = sm;                    // [BQ][QKS]
    float* Ks   = Qs + BQ * QKS;         // [BKT][QKS]
    float* Vs   = Ks + BKT * QKS;        // [BKT][QKS]
    float* Ss   = Vs + BKT * QKS;        // [BQ][SST]
    float* rowm = Ss + BQ * SST;
    float* rowl = rowm + BQ;
    float* rowc = rowl + BQ;

    const int tid = threadIdx.x;
    const int qi  = blockIdx.x;          // query tile index, 0..31
    const int bh  = blockIdx.y;          // b*NH + h, 0..63

    const float* Qg = g_q + (size_t)bh * T_ * HD_ + (size_t)qi * BQ * HD_;
    const float* Kg = g_k + (size_t)bh * T_ * HD_;
    const float* Vg = g_v + (size_t)bh * T_ * HD_;

    // Load Q tile (64x64 floats = 1024 float4s, 4 per thread)
#pragma unroll
    for (int k = 0; k < 4; k++) {
        const int idx = tid + k * 256;
        const int r = idx >> 4, c4 = idx & 15;
        *(float4*)&Qs[r * QKS + c4 * 4] = *(const float4*)(Qg + r * HD_ + c4 * 4);
    }
    if (tid < BQ) { rowm[tid] = -INFINITY; rowl[tid] = 0.f; }

    const int tr = tid >> 4, tc = tid & 15;
    const int r0 = tr * 4, c0 = tc * 4;

    float o[4][4];
#pragma unroll
    for (int i = 0; i < 4; i++)
#pragma unroll
        for (int j = 0; j < 4; j++) o[i][j] = 0.f;

    __syncthreads();

    for (int kt = 0; kt <= qi; kt++) {
        // Load K, V tiles
#pragma unroll
        for (int k = 0; k < 4; k++) {
            const int idx = tid + k * 256;
            const int r = idx >> 4, c4 = idx & 15;
            *(float4*)&Ks[r * QKS + c4 * 4] =
                *(const float4*)(Kg + (size_t)(kt * BKT + r) * HD_ + c4 * 4);
            *(float4*)&Vs[r * QKS + c4 * 4] =
                *(const float4*)(Vg + (size_t)(kt * BKT + r) * HD_ + c4 * 4);
        }
        __syncthreads();

        // S = Q @ K^T (4x4 microtile per thread)
        float s[4][4];
#pragma unroll
        for (int i = 0; i < 4; i++)
#pragma unroll
            for (int j = 0; j < 4; j++) s[i][j] = 0.f;

#pragma unroll
        for (int d = 0; d < HD_; d += 4) {
            float qr[4][4], kr[4][4];
#pragma unroll
            for (int i = 0; i < 4; i++) {
                float4 t = *(const float4*)&Qs[(r0 + i) * QKS + d];
                qr[i][0] = t.x; qr[i][1] = t.y; qr[i][2] = t.z; qr[i][3] = t.w;
            }
#pragma unroll
            for (int j = 0; j < 4; j++) {
                float4 t = *(const float4*)&Ks[(c0 + j) * QKS + d];
                kr[j][0] = t.x; kr[j][1] = t.y; kr[j][2] = t.z; kr[j][3] = t.w;
            }
#pragma unroll
            for (int i = 0; i < 4; i++)
#pragma unroll
                for (int j = 0; j < 4; j++)
#pragma unroll
                    for (int e = 0; e < 4; e++)
                        s[i][j] += qr[i][e] * kr[j][e];
        }

        const float scale = 0.125f;  // 1/sqrt(64)
        const bool diag = (kt == qi);
#pragma unroll
        for (int i = 0; i < 4; i++)
#pragma unroll
            for (int j = 0; j < 4; j++) {
                float val = s[i][j] * scale;
                if (diag && (c0 + j > r0 + i)) val = -INFINITY;
                Ss[(r0 + i) * SST + (c0 + j)] = val;
            }
        __syncthreads();

        // Online softmax per row (64 threads, one row each)
        if (tid < BQ) {
            const int r = tid;
            const float mold = rowm[r];
            float mx = mold;
#pragma unroll 8
            for (int j = 0; j < BKT; j++) mx = fmaxf(mx, Ss[r * SST + j]);
            const float corr = __expf(mold - mx);
            float sum = 0.f;
#pragma unroll 8
            for (int j = 0; j < BKT; j++) {
                const float p = __expf(Ss[r * SST + j] - mx);
                Ss[r * SST + j] = p;
                sum += p;
            }
            rowm[r] = mx;
            rowl[r] = rowl[r] * corr + sum;
            rowc[r] = corr;
        }
        __syncthreads();

        // O = O * corr + P @ V
        float cr[4];
#pragma unroll
        for (int i = 0; i < 4; i++) cr[i] = rowc[r0 + i];
#pragma unroll
        for (int i = 0; i < 4; i++)
#pragma unroll
            for (int j = 0; j < 4; j++) o[i][j] *= cr[i];

#pragma unroll 4
        for (int jk = 0; jk < BKT; jk++) {
            const float4 vv = *(const float4*)&Vs[jk * QKS + c0];
            float p[4];
#pragma unroll
            for (int i = 0; i < 4; i++) p[i] = Ss[(r0 + i) * SST + jk];
#pragma unroll
            for (int i = 0; i < 4; i++) {
                o[i][0] += p[i] * vv.x;
                o[i][1] += p[i] * vv.y;
                o[i][2] += p[i] * vv.z;
                o[i][3] += p[i] * vv.w;
            }
        }
        __syncthreads();
    }

    // Normalize and write to [B, T, C] layout
    const int b = bh >> 4, h = bh & 15;
#pragma unroll
    for (int i = 0; i < 4; i++) {
        const int t = qi * BQ + r0 + i;
        const float inv = 1.f / rowl[r0 + i];
        float4 v;
        v.x = o[i][0] * inv;
        v.y = o[i][1] * inv;
        v.z = o[i][2] * inv;
        v.w = o[i][3] * inv;
        *(float4*)&g_att[((size_t)(b * T_ + t)) * C_ + h * HD_ + c0] = v;
    }
}

// ---------------------------------------------------------------------------
// Launch
// ---------------------------------------------------------------------------
extern "C" void kernel_launch(void* const* d_in, const int* in_sizes, int n_in,
                              void* d_out, int out_size)
{
    const float* x      = (const float*)d_in[0];
    const float* w_attn = (const float*)d_in[1];
    const float* b_attn = (const float*)d_in[2];
    const float* w_proj = (const float*)d_in[3];
    const float* b_proj = (const float*)d_in[4];
    float* out = (float*)d_out;

    cudaFuncSetAttribute(flash_kernel,
                         cudaFuncAttributeMaxDynamicSharedMemorySize, FLASH_SMEM);

    dim3 block(256);
    // QKV GEMM: M=8192, N=3072
    sgemm_kernel<3072, true><<<dim3(3072 / BN, M_ / BM), block>>>(x, w_attn, b_attn, nullptr);
    // Flash attention: 32 q-tiles x 64 (b,h) pairs
    flash_kernel<<<dim3(T_ / BQ, B_ * NH_), dim3(256), FLASH_SMEM>>>();
    // Output projection: M=8192, N=1024
    sgemm_kernel<1024, false><<<dim3(1024 / BN, M_ / BM), block>>>(nullptr, w_proj, b_proj, out);
}

// round 4
// speedup vs baseline: 1.0268x; 1.0268x over previous
#include <cuda_runtime.h>
#include <cuda.h>
#include <math.h>
#include <stdint.h>

#define B_   4
#define T_   2048
#define C_   1024
#define NH_  16
#define HD_  64
#define M_   (B_*T_)      // 8192

// Scratch (allocation-free: __device__ globals)
__device__ float g_q[B_*NH_*T_*HD_];
__device__ float g_k[B_*NH_*T_*HD_];
__device__ float g_v[B_*NH_*T_*HD_];
__device__ float g_att[M_*C_];
__device__ float g_wt[3*C_*C_];    // w_attn^T  [3072][1024]
__device__ float g_wtp[C_*C_];     // w_proj^T  [1024][1024]

// ===========================================================================
// Helpers
// ===========================================================================
// tf32 Dekker split (hi = rna-rounded tf32, lo = residual as tf32)
__device__ __forceinline__ float tf32_rd(float x) {
    uint32_t u; asm("cvt.rna.tf32.f32 %0, %1;" : "=r"(u) : "f"(x));
    return __uint_as_float(u);
}
__device__ __forceinline__ void split4(float4 x, float4& h, float4& l) {
    h.x = tf32_rd(x.x); l.x = tf32_rd(x.x - h.x);
    h.y = tf32_rd(x.y); l.y = tf32_rd(x.y - h.y);
    h.z = tf32_rd(x.z); l.z = tf32_rd(x.z - h.z);
    h.w = tf32_rd(x.w); l.w = tf32_rd(x.w - h.w);
}

#define MMA_TF32(c, a0v, a1v, a2v, a3v, b0v, b1v) \
    asm volatile("mma.sync.aligned.m16n8k8.row.col.f32.tf32.tf32.f32 " \
        "{%0,%1,%2,%3}, {%4,%5,%6,%7}, {%8,%9}, {%0,%1,%2,%3};" \
        : "+f"((c)[0]), "+f"((c)[1]), "+f"((c)[2]), "+f"((c)[3]) \
        : "r"(a0v), "r"(a1v), "r"(a2v), "r"(a3v), "r"(b0v), "r"(b1v))

// ===========================================================================
// Transpose: out[c][r] = in[r][c]
// ===========================================================================
__global__ __launch_bounds__(256)
void transpose_k(const float* __restrict__ in, float* __restrict__ out, int R, int C)
{
    __shared__ float t[32][33];
    int x  = blockIdx.x * 32 + threadIdx.x;
    int y0 = blockIdx.y * 32 + threadIdx.y;
#pragma unroll
    for (int i = 0; i < 32; i += 8)
        t[threadIdx.y + i][threadIdx.x] = in[(size_t)(y0 + i) * C + x];
    __syncthreads();
    int x2 = blockIdx.y * 32 + threadIdx.x;
    int y2 = blockIdx.x * 32 + threadIdx.y;
#pragma unroll
    for (int i = 0; i < 32; i += 8)
        out[(size_t)(y2 + i) * R + x2] = t[threadIdx.x][threadIdx.y + i];
}

// ===========================================================================
// HMMA tf32 GEMM (3xTF32): D[M,N] = A[M,K] @ WT[N,K]^T + bias
//   Tile 128x128x16, 8 warps (2m x 4n), warp tile 64x32, mma m16n8k8.
//   Fragments loaded with plain LDS.32 at documented fragment coordinates.
// ===========================================================================
#define APAD 20   // smem row stride in floats -> 8rowx4col warp access is conflict-free

template<int NTOT, bool QKV>
__global__ __launch_bounds__(256)
void hmma_gemm(const float* __restrict__ Ain, const float* __restrict__ WT,
               const float* __restrict__ bias, float* __restrict__ out)
{
    __shared__ float Ahi_s[128*APAD], Alo_s[128*APAD];
    __shared__ float Bhi_s[128*APAD], Blo_s[128*APAD];

    const int tid  = threadIdx.x;
    const int lane = tid & 31;
    const int wid  = tid >> 5;
    const int wm   = wid & 1;        // m half (0/1): 64 rows
    const int wn   = wid >> 1;       // n quarter (0..3): 32 cols
    const int m0   = blockIdx.y * 128;
    const int n0   = blockIdx.x * 128;
    const int g    = lane >> 2;      // 0..7
    const int tig  = lane & 3;       // 0..3

    const float* A = QKV ? Ain : (const float*)g_att;   // device-side symbol access

    float acc[4][4][4];
#pragma unroll
    for (int i = 0; i < 4; i++)
#pragma unroll
        for (int j = 0; j < 4; j++)
#pragma unroll
            for (int e = 0; e < 4; e++) acc[i][j][e] = 0.f;

    const float* Ap = A  + (size_t)m0 * 1024;
    const float* Wp = WT + (size_t)n0 * 1024;

    for (int kc = 0; kc < 64; kc++) {
        // ---- load 128x16 of A and W, split hi/lo, stage to smem ----
#pragma unroll
        for (int h = 0; h < 2; h++) {
            const int idx = tid + h * 256;
            const int row = idx >> 2, c4 = idx & 3;
            float4 a = *(const float4*)(Ap + (size_t)row * 1024 + kc * 16 + c4 * 4);
            float4 hi, lo; split4(a, hi, lo);
            *(float4*)&Ahi_s[row * APAD + c4 * 4] = hi;
            *(float4*)&Alo_s[row * APAD + c4 * 4] = lo;
            float4 b = *(const float4*)(Wp + (size_t)row * 1024 + kc * 16 + c4 * 4);
            split4(b, hi, lo);
            *(float4*)&Bhi_s[row * APAD + c4 * 4] = hi;
            *(float4*)&Blo_s[row * APAD + c4 * 4] = lo;
        }
        __syncthreads();

        // ---- two k8 steps of HMMA ----
#pragma unroll
        for (int ks = 0; ks < 2; ks++) {
            const int k0 = ks * 8;

            // A fragments (4 m-tiles, hi + lo), direct LDS at fragment coords
            uint32_t ah[4][4], al[4][4];
#pragma unroll
            for (int mt = 0; mt < 4; mt++) {
                const int r = wm * 64 + mt * 16;
                const int base0 = (r + g)     * APAD + k0 + tig;
                const int base1 = (r + 8 + g) * APAD + k0 + tig;
                ah[mt][0] = __float_as_uint(Ahi_s[base0]);
                ah[mt][1] = __float_as_uint(Ahi_s[base1]);
                ah[mt][2] = __float_as_uint(Ahi_s[base0 + 4]);
                ah[mt][3] = __float_as_uint(Ahi_s[base1 + 4]);
                al[mt][0] = __float_as_uint(Alo_s[base0]);
                al[mt][1] = __float_as_uint(Alo_s[base1]);
                al[mt][2] = __float_as_uint(Alo_s[base0 + 4]);
                al[mt][3] = __float_as_uint(Alo_s[base1 + 4]);
            }

#pragma unroll
            for (int nt = 0; nt < 4; nt++) {
                // B fragment: b0 at (k=k0+tig, n=nrow+g) = WT[nrow+g][k0+tig]
                const int nb = (wn * 32 + nt * 8 + g) * APAD + k0 + tig;
                const uint32_t bh0 = __float_as_uint(Bhi_s[nb]);
                const uint32_t bh1 = __float_as_uint(Bhi_s[nb + 4]);
                const uint32_t bl0 = __float_as_uint(Blo_s[nb]);
                const uint32_t bl1 = __float_as_uint(Blo_s[nb + 4]);
#pragma unroll
                for (int mt = 0; mt < 4; mt++) {
                    MMA_TF32(acc[mt][nt], ah[mt][0], ah[mt][1], ah[mt][2], ah[mt][3], bh0, bh1); // hi*hi
                    MMA_TF32(acc[mt][nt], al[mt][0], al[mt][1], al[mt][2], al[mt][3], bh0, bh1); // lo*hi
                    MMA_TF32(acc[mt][nt], ah[mt][0], ah[mt][1], ah[mt][2], ah[mt][3], bl0, bl1); // hi*lo
                }
            }
        }
        __syncthreads();
    }

    // ---- epilogue: c0,c1 at (row=g, col=2*tig+{0,1}); c2,c3 at row g+8 ----
#pragma unroll
    for (int mt = 0; mt < 4; mt++) {
#pragma unroll
        for (int nt = 0; nt < 4; nt++) {
            const int n = n0 + wn * 32 + nt * 8 + tig * 2;
            const float bx = bias[n], by = bias[n + 1];
#pragma unroll
            for (int half = 0; half < 2; half++) {
                const int m = m0 + wm * 64 + mt * 16 + g + half * 8;
                float2 v;
                v.x = acc[mt][nt][half * 2 + 0] + bx;
                v.y = acc[mt][nt][half * 2 + 1] + by;
                if (QKV) {
                    const int bb = m >> 11;
                    const int tt = m & (T_ - 1);
                    const int which = n >> 10;
                    const int cc = n & (C_ - 1);
                    const int h = cc >> 6;
                    const int d = cc & (HD_ - 1);
                    float* dst = (which == 0) ? g_q : (which == 1) ? g_k : g_v;
                    *(float2*)&dst[(((size_t)(bb * NH_ + h)) * T_ + tt) * HD_ + d] = v;
                } else {
                    *(float2*)&out[(size_t)m * NTOT + n] = v;
                }
            }
        }
    }
}

// ===========================================================================
// Flash attention (fp32, online softmax) — unchanged validated kernel
// ===========================================================================
#define BQ  64
#define BKT 64
#define QKS 68
#define SST 67
#define FLASH_SMEM ((3*BQ*QKS + BQ*SST + 3*BQ) * (int)sizeof(float))

__global__ __launch_bounds__(256)
void flash_kernel()
{
    extern __shared__ float sm[];
    float* Qs   = sm;
    float* Ks   = Qs + BQ * QKS;
    float* Vs   = Ks + BKT * QKS;
    float* Ss   = Vs + BKT * QKS;
    float* rowm = Ss + BQ * SST;
    float* rowl = rowm + BQ;
    float* rowc = rowl + BQ;

    const int tid = threadIdx.x;
    const int qi  = blockIdx.x;
    const int bh  = blockIdx.y;

    const float* Qg = g_q + (size_t)bh * T_ * HD_ + (size_t)qi * BQ * HD_;
    const float* Kg = g_k + (size_t)bh * T_ * HD_;
    const float* Vg = g_v + (size_t)bh * T_ * HD_;

#pragma unroll
    for (int k = 0; k < 4; k++) {
        const int idx = tid + k * 256;
        const int r = idx >> 4, c4 = idx & 15;
        *(float4*)&Qs[r * QKS + c4 * 4] = *(const float4*)(Qg + r * HD_ + c4 * 4);
    }
    if (tid < BQ) { rowm[tid] = -INFINITY; rowl[tid] = 0.f; }

    const int tr = tid >> 4, tc = tid & 15;
    const int r0 = tr * 4, c0 = tc * 4;

    float o[4][4];
#pragma unroll
    for (int i = 0; i < 4; i++)
#pragma unroll
        for (int j = 0; j < 4; j++) o[i][j] = 0.f;

    __syncthreads();

    for (int kt = 0; kt <= qi; kt++) {
#pragma unroll
        for (int k = 0; k < 4; k++) {
            const int idx = tid + k * 256;
            const int r = idx >> 4, c4 = idx & 15;
            *(float4*)&Ks[r * QKS + c4 * 4] =
                *(const float4*)(Kg + (size_t)(kt * BKT + r) * HD_ + c4 * 4);
            *(float4*)&Vs[r * QKS + c4 * 4] =
                *(const float4*)(Vg + (size_t)(kt * BKT + r) * HD_ + c4 * 4);
        }
        __syncthreads();

        float s[4][4];
#pragma unroll
        for (int i = 0; i < 4; i++)
#pragma unroll
            for (int j = 0; j < 4; j++) s[i][j] = 0.f;

#pragma unroll
        for (int d = 0; d < HD_; d += 4) {
            float qr[4][4], kr[4][4];
#pragma unroll
            for (int i = 0; i < 4; i++) {
                float4 t = *(const float4*)&Qs[(r0 + i) * QKS + d];
                qr[i][0] = t.x; qr[i][1] = t.y; qr[i][2] = t.z; qr[i][3] = t.w;
            }
#pragma unroll
            for (int j = 0; j < 4; j++) {
                float4 t = *(const float4*)&Ks[(c0 + j) * QKS + d];
                kr[j][0] = t.x; kr[j][1] = t.y; kr[j][2] = t.z; kr[j][3] = t.w;
            }
#pragma unroll
            for (int i = 0; i < 4; i++)
#pragma unroll
                for (int j = 0; j < 4; j++)
#pragma unroll
                    for (int e = 0; e < 4; e++)
                        s[i][j] += qr[i][e] * kr[j][e];
        }

        const float scale = 0.125f;
        const bool diag = (kt == qi);
#pragma unroll
        for (int i = 0; i < 4; i++)
#pragma unroll
            for (int j = 0; j < 4; j++) {
                float val = s[i][j] * scale;
                if (diag && (c0 + j > r0 + i)) val = -INFINITY;
                Ss[(r0 + i) * SST + (c0 + j)] = val;
            }
        __syncthreads();

        if (tid < BQ) {
            const int r = tid;
            const float mold = rowm[r];
            float mx = mold;
#pragma unroll 8
            for (int j = 0; j < BKT; j++) mx = fmaxf(mx, Ss[r * SST + j]);
            const float corr = __expf(mold - mx);
            float sum = 0.f;
#pragma unroll 8
            for (int j = 0; j < BKT; j++) {
                const float p = __expf(Ss[r * SST + j] - mx);
                Ss[r * SST + j] = p;
                sum += p;
            }
            rowm[r] = mx;
            rowl[r] = rowl[r] * corr + sum;
            rowc[r] = corr;
        }
        __syncthreads();

        float cr[4];
#pragma unroll
        for (int i = 0; i < 4; i++) cr[i] = rowc[r0 + i];
#pragma unroll
        for (int i = 0; i < 4; i++)
#pragma unroll
            for (int j = 0; j < 4; j++) o[i][j] *= cr[i];

#pragma unroll 4
        for (int jk = 0; jk < BKT; jk++) {
            const float4 vv = *(const float4*)&Vs[jk * QKS + c0];
            float p[4];
#pragma unroll
            for (int i = 0; i < 4; i++) p[i] = Ss[(r0 + i) * SST + jk];
#pragma unroll
            for (int i = 0; i < 4; i++) {
                o[i][0] += p[i] * vv.x;
                o[i][1] += p[i] * vv.y;
                o[i][2] += p[i] * vv.z;
                o[i][3] += p[i] * vv.w;
            }
        }
        __syncthreads();
    }

    const int b = bh >> 4, h = bh & 15;
#pragma unroll
    for (int i = 0; i < 4; i++) {
        const int t = qi * BQ + r0 + i;
        const float inv = 1.f / rowl[r0 + i];
        float4 v;
        v.x = o[i][0] * inv;
        v.y = o[i][1] * inv;
        v.z = o[i][2] * inv;
        v.w = o[i][3] * inv;
        *(float4*)&g_att[((size_t)(b * T_ + t)) * C_ + h * HD_ + c0] = v;
    }
}

// ===========================================================================
// Launch
// ===========================================================================
extern "C" void kernel_launch(void* const* d_in, const int* in_sizes, int n_in,
                              void* d_out, int out_size)
{
    const float* x      = (const float*)d_in[0];
    const float* w_attn = (const float*)d_in[1];
    const float* b_attn = (const float*)d_in[2];
    const float* w_proj = (const float*)d_in[3];
    const float* b_proj = (const float*)d_in[4];
    float* out = (float*)d_out;

    float* wt  = nullptr;  cudaGetSymbolAddress((void**)&wt,  g_wt);
    float* wtp = nullptr;  cudaGetSymbolAddress((void**)&wtp, g_wtp);

    cudaFuncSetAttribute(flash_kernel,
                         cudaFuncAttributeMaxDynamicSharedMemorySize, FLASH_SMEM);

    // Transpose weights to K-major
    transpose_k<<<dim3(3072/32, 1024/32), dim3(32, 8)>>>(w_attn, wt, 1024, 3072);
    transpose_k<<<dim3(1024/32, 1024/32), dim3(32, 8)>>>(w_proj, wtp, 1024, 1024);

    // QKV GEMM: M=8192, N=3072 (HMMA tf32 3x)
    hmma_gemm<3072, true><<<dim3(3072/128, M_/128), 256>>>(x, wt, b_attn, nullptr);

    // Flash attention
    flash_kernel<<<dim3(T_/BQ, B_*NH_), 256, FLASH_SMEM>>>();

    // Output projection: M=8192, N=1024 (A read from g_att inside the kernel)
    hmma_gemm<1024, false><<<dim3(1024/128, M_/128), 256>>>(nullptr, wtp, b_proj, out);
}

// round 5
// speedup vs baseline: 1.5207x; 1.4810x over previous
#include <cuda_runtime.h>
#include <cuda.h>
#include <math.h>
#include <stdint.h>

#define B_   4
#define T_   2048
#define C_   1024
#define NH_  16
#define HD_  64
#define M_   (B_*T_)      // 8192

// Scratch (allocation-free: __device__ globals)
__device__ float g_q[B_*NH_*T_*HD_];
__device__ float g_k[B_*NH_*T_*HD_];
__device__ float g_v[B_*NH_*T_*HD_];
__device__ float g_att[M_*C_];
__device__ float g_wt[3*C_*C_];    // w_attn^T  [3072][1024]
__device__ float g_wtp[C_*C_];     // w_proj^T  [1024][1024]

// ===========================================================================
// Helpers
// ===========================================================================
__device__ __forceinline__ float tf32_rd(float x) {
    uint32_t u; asm("cvt.rna.tf32.f32 %0, %1;" : "=r"(u) : "f"(x));
    return __uint_as_float(u);
}
__device__ __forceinline__ void split4(float4 x, float4& h, float4& l) {
    h.x = tf32_rd(x.x); l.x = tf32_rd(x.x - h.x);
    h.y = tf32_rd(x.y); l.y = tf32_rd(x.y - h.y);
    h.z = tf32_rd(x.z); l.z = tf32_rd(x.z - h.z);
    h.w = tf32_rd(x.w); l.w = tf32_rd(x.w - h.w);
}

#define MMA_TF32(c, a0v, a1v, a2v, a3v, b0v, b1v) \
    asm volatile("mma.sync.aligned.m16n8k8.row.col.f32.tf32.tf32.f32 " \
        "{%0,%1,%2,%3}, {%4,%5,%6,%7}, {%8,%9}, {%0,%1,%2,%3};" \
        : "+f"((c)[0]), "+f"((c)[1]), "+f"((c)[2]), "+f"((c)[3]) \
        : "r"(a0v), "r"(a1v), "r"(a2v), "r"(a3v), "r"(b0v), "r"(b1v))

// ===========================================================================
// Transpose: out[c][r] = in[r][c]
// ===========================================================================
__global__ __launch_bounds__(256)
void transpose_k(const float* __restrict__ in, float* __restrict__ out, int R, int C)
{
    __shared__ float t[32][33];
    int x  = blockIdx.x * 32 + threadIdx.x;
    int y0 = blockIdx.y * 32 + threadIdx.y;
#pragma unroll
    for (int i = 0; i < 32; i += 8)
        t[threadIdx.y + i][threadIdx.x] = in[(size_t)(y0 + i) * C + x];
    __syncthreads();
    int x2 = blockIdx.y * 32 + threadIdx.x;
    int y2 = blockIdx.x * 32 + threadIdx.y;
#pragma unroll
    for (int i = 0; i < 32; i += 8)
        out[(size_t)(y2 + i) * R + x2] = t[threadIdx.x][threadIdx.y + i];
}

// ===========================================================================
// HMMA tf32 GEMM (3xTF32) — unchanged from passing R4 kernel
// ===========================================================================
#define APAD 20

template<int NTOT, bool QKV>
__global__ __launch_bounds__(256)
void hmma_gemm(const float* __restrict__ Ain, const float* __restrict__ WT,
               const float* __restrict__ bias, float* __restrict__ out)
{
    __shared__ float Ahi_s[128*APAD], Alo_s[128*APAD];
    __shared__ float Bhi_s[128*APAD], Blo_s[128*APAD];

    const int tid  = threadIdx.x;
    const int lane = tid & 31;
    const int wid  = tid >> 5;
    const int wm   = wid & 1;
    const int wn   = wid >> 1;
    const int m0   = blockIdx.y * 128;
    const int n0   = blockIdx.x * 128;
    const int g    = lane >> 2;
    const int tig  = lane & 3;

    const float* A = QKV ? Ain : (const float*)g_att;

    float acc[4][4][4];
#pragma unroll
    for (int i = 0; i < 4; i++)
#pragma unroll
        for (int j = 0; j < 4; j++)
#pragma unroll
            for (int e = 0; e < 4; e++) acc[i][j][e] = 0.f;

    const float* Ap = A  + (size_t)m0 * 1024;
    const float* Wp = WT + (size_t)n0 * 1024;

    for (int kc = 0; kc < 64; kc++) {
#pragma unroll
        for (int h = 0; h < 2; h++) {
            const int idx = tid + h * 256;
            const int row = idx >> 2, c4 = idx & 3;
            float4 a = *(const float4*)(Ap + (size_t)row * 1024 + kc * 16 + c4 * 4);
            float4 hi, lo; split4(a, hi, lo);
            *(float4*)&Ahi_s[row * APAD + c4 * 4] = hi;
            *(float4*)&Alo_s[row * APAD + c4 * 4] = lo;
            float4 b = *(const float4*)(Wp + (size_t)row * 1024 + kc * 16 + c4 * 4);
            split4(b, hi, lo);
            *(float4*)&Bhi_s[row * APAD + c4 * 4] = hi;
            *(float4*)&Blo_s[row * APAD + c4 * 4] = lo;
        }
        __syncthreads();

#pragma unroll
        for (int ks = 0; ks < 2; ks++) {
            const int k0 = ks * 8;
            uint32_t ah[4][4], al[4][4];
#pragma unroll
            for (int mt = 0; mt < 4; mt++) {
                const int r = wm * 64 + mt * 16;
                const int base0 = (r + g)     * APAD + k0 + tig;
                const int base1 = (r + 8 + g) * APAD + k0 + tig;
                ah[mt][0] = __float_as_uint(Ahi_s[base0]);
                ah[mt][1] = __float_as_uint(Ahi_s[base1]);
                ah[mt][2] = __float_as_uint(Ahi_s[base0 + 4]);
                ah[mt][3] = __float_as_uint(Ahi_s[base1 + 4]);
                al[mt][0] = __float_as_uint(Alo_s[base0]);
                al[mt][1] = __float_as_uint(Alo_s[base1]);
                al[mt][2] = __float_as_uint(Alo_s[base0 + 4]);
                al[mt][3] = __float_as_uint(Alo_s[base1 + 4]);
            }
#pragma unroll
            for (int nt = 0; nt < 4; nt++) {
                const int nb = (wn * 32 + nt * 8 + g) * APAD + k0 + tig;
                const uint32_t bh0 = __float_as_uint(Bhi_s[nb]);
                const uint32_t bh1 = __float_as_uint(Bhi_s[nb + 4]);
                const uint32_t bl0 = __float_as_uint(Blo_s[nb]);
                const uint32_t bl1 = __float_as_uint(Blo_s[nb + 4]);
#pragma unroll
                for (int mt = 0; mt < 4; mt++) {
                    MMA_TF32(acc[mt][nt], ah[mt][0], ah[mt][1], ah[mt][2], ah[mt][3], bh0, bh1);
                    MMA_TF32(acc[mt][nt], al[mt][0], al[mt][1], al[mt][2], al[mt][3], bh0, bh1);
                    MMA_TF32(acc[mt][nt], ah[mt][0], ah[mt][1], ah[mt][2], ah[mt][3], bl0, bl1);
                }
            }
        }
        __syncthreads();
    }

#pragma unroll
    for (int mt = 0; mt < 4; mt++) {
#pragma unroll
        for (int nt = 0; nt < 4; nt++) {
            const int n = n0 + wn * 32 + nt * 8 + tig * 2;
            const float bx = bias[n], by = bias[n + 1];
#pragma unroll
            for (int half = 0; half < 2; half++) {
                const int m = m0 + wm * 64 + mt * 16 + g + half * 8;
                float2 v;
                v.x = acc[mt][nt][half * 2 + 0] + bx;
                v.y = acc[mt][nt][half * 2 + 1] + by;
                if (QKV) {
                    const int bb = m >> 11;
                    const int tt = m & (T_ - 1);
                    const int which = n >> 10;
                    const int cc = n & (C_ - 1);
                    const int h = cc >> 6;
                    const int d = cc & (HD_ - 1);
                    float* dst = (which == 0) ? g_q : (which == 1) ? g_k : g_v;
                    *(float2*)&dst[(((size_t)(bb * NH_ + h)) * T_ + tt) * HD_ + d] = v;
                } else {
                    *(float2*)&out[(size_t)m * NTOT + n] = v;
                }
            }
        }
    }
}

// ===========================================================================
// HMMA flash attention: BQ=64, BK=32, 8 warps (4m x 2n), register softmax.
//   QK^T: 3xTF32.  PV: P_hi @ (V_hi + V_lo)  (V exact, P tf32-rounded).
// Smem float offsets:
//   Qhi 0, Qlo 4352, Khi 8704, Klo 10880, Vhi 13056, Vlo 15360,
//   Ps 17664 (64x36), rowm 19968, rowl 20032, smax 20096(128), ssum 20224(128)
// ===========================================================================
#define FL_QLD 68
#define FL_KLD 68
#define FL_VLD 72
#define FL_PLD 36
#define FL_SMEM (20352 * 4)

__global__ __launch_bounds__(256)
void flash_hmma()
{
    extern __shared__ float sm[];
    float* Qhi = sm;
    float* Qlo = sm + 4352;
    float* Khi = sm + 8704;
    float* Klo = sm + 10880;
    float* Vhi = sm + 13056;
    float* Vlo = sm + 15360;
    float* Ps  = sm + 17664;
    float* rowm = sm + 19968;
    float* rowl = sm + 20032;
    float* smax = sm + 20096;   // [2][64]
    float* ssum = sm + 20224;   // [2][64]

    const int tid  = threadIdx.x;
    const int lane = tid & 31;
    const int wid  = tid >> 5;
    const int wm   = wid & 3;        // m-tile (16 rows)
    const int wn   = wid >> 2;       // n-half (16 cols for S, 32 for O)
    const int g    = lane >> 2;
    const int tig  = lane & 3;

    const int qi = blockIdx.x;       // 0..31
    const int bh = blockIdx.y;       // 0..63
    const int q0 = qi * 64;

    const float* Qg = g_q + (size_t)bh * T_ * HD_ + (size_t)q0 * HD_;
    const float* Kg = g_k + (size_t)bh * T_ * HD_;
    const float* Vg = g_v + (size_t)bh * T_ * HD_;

    // load Q (64x64) + split
#pragma unroll
    for (int it = 0; it < 4; it++) {
        const int idx = tid + it * 256;
        const int r = idx >> 4, c4 = idx & 15;
        float4 v = *(const float4*)(Qg + r * HD_ + c4 * 4);
        float4 h, l; split4(v, h, l);
        *(float4*)&Qhi[r * FL_QLD + c4 * 4] = h;
        *(float4*)&Qlo[r * FL_QLD + c4 * 4] = l;
    }
    if (tid < 64) { rowm[tid] = -INFINITY; rowl[tid] = 0.f; }

    const int rlo = wm * 16 + g;       // local row (c0,c1)
    const int rhi = rlo + 8;           // local row (c2,c3)

    float o[4][4];
#pragma unroll
    for (int nt = 0; nt < 4; nt++)
#pragma unroll
        for (int e = 0; e < 4; e++) o[nt][e] = 0.f;

    __syncthreads();

    const int nkt = 2 * qi + 2;
    for (int kt = 0; kt < nkt; kt++) {
        // load K,V tile (32x64 each) + split
#pragma unroll
        for (int it = 0; it < 2; it++) {
            const int idx = tid + it * 256;
            const int r = idx >> 4, c4 = idx & 15;
            float4 kv = *(const float4*)(Kg + (size_t)(kt * 32 + r) * HD_ + c4 * 4);
            float4 h, l; split4(kv, h, l);
            *(float4*)&Khi[r * FL_KLD + c4 * 4] = h;
            *(float4*)&Klo[r * FL_KLD + c4 * 4] = l;
            float4 vv = *(const float4*)(Vg + (size_t)(kt * 32 + r) * HD_ + c4 * 4);
            split4(vv, h, l);
            *(float4*)&Vhi[r * FL_VLD + c4 * 4] = h;
            *(float4*)&Vlo[r * FL_VLD + c4 * 4] = l;
        }
        __syncthreads();   // (A) K/V ready

        // ---- S = Q @ K^T  (3xTF32), warp tile 16x16 ----
        float s[2][4];
#pragma unroll
        for (int nt = 0; nt < 2; nt++)
#pragma unroll
            for (int e = 0; e < 4; e++) s[nt][e] = 0.f;

#pragma unroll
        for (int ks = 0; ks < 8; ks++) {
            const int k0 = ks * 8;
            const int a0i = rlo * FL_QLD + k0 + tig;
            const int a1i = rhi * FL_QLD + k0 + tig;
            const uint32_t ah0 = __float_as_uint(Qhi[a0i]);
            const uint32_t ah1 = __float_as_uint(Qhi[a1i]);
            const uint32_t ah2 = __float_as_uint(Qhi[a0i + 4]);
            const uint32_t ah3 = __float_as_uint(Qhi[a1i + 4]);
            const uint32_t al0 = __float_as_uint(Qlo[a0i]);
            const uint32_t al1 = __float_as_uint(Qlo[a1i]);
            const uint32_t al2 = __float_as_uint(Qlo[a0i + 4]);
            const uint32_t al3 = __float_as_uint(Qlo[a1i + 4]);
#pragma unroll
            for (int nt = 0; nt < 2; nt++) {
                const int nb = (wn * 16 + nt * 8 + g) * FL_KLD + k0 + tig;
                const uint32_t bh0 = __float_as_uint(Khi[nb]);
                const uint32_t bh1 = __float_as_uint(Khi[nb + 4]);
                const uint32_t bl0 = __float_as_uint(Klo[nb]);
                const uint32_t bl1 = __float_as_uint(Klo[nb + 4]);
                MMA_TF32(s[nt], ah0, ah1, ah2, ah3, bh0, bh1);
                MMA_TF32(s[nt], al0, al1, al2, al3, bh0, bh1);
                MMA_TF32(s[nt], ah0, ah1, ah2, ah3, bl0, bl1);
            }
        }

        // ---- scale + causal mask ----
        const int qrow_lo = q0 + rlo;
        const int qrow_hi = q0 + rhi;
        float mlo = -INFINITY, mhi = -INFINITY;
#pragma unroll
        for (int nt = 0; nt < 2; nt++) {
            const int colb = kt * 32 + wn * 16 + nt * 8 + 2 * tig;
#pragma unroll
            for (int j = 0; j < 2; j++) {
                float v0 = s[nt][j] * 0.125f;
                if (colb + j > qrow_lo) v0 = -INFINITY;
                s[nt][j] = v0;
                mlo = fmaxf(mlo, v0);
                float v1 = s[nt][2 + j] * 0.125f;
                if (colb + j > qrow_hi) v1 = -INFINITY;
                s[nt][2 + j] = v1;
                mhi = fmaxf(mhi, v1);
            }
        }
        // quad reduce (lanes 4g..4g+3 share a row)
#pragma unroll
        for (int off = 1; off < 4; off <<= 1) {
            mlo = fmaxf(mlo, __shfl_xor_sync(0xffffffffu, mlo, off));
            mhi = fmaxf(mhi, __shfl_xor_sync(0xffffffffu, mhi, off));
        }
        if (tig == 0) { smax[wn * 64 + rlo] = mlo; smax[wn * 64 + rhi] = mhi; }
        __syncthreads();   // (B)

        // ---- combine stats, exp, write P ----
        const float mold_lo = rowm[rlo];
        const float mold_hi = rowm[rhi];
        const float mnew_lo = fmaxf(mold_lo, fmaxf(smax[rlo], smax[64 + rlo]));
        const float mnew_hi = fmaxf(mold_hi, fmaxf(smax[rhi], smax[64 + rhi]));
        const float corr_lo = __expf(mold_lo - mnew_lo);
        const float corr_hi = __expf(mold_hi - mnew_hi);

        float sumlo = 0.f, sumhi = 0.f;
#pragma unroll
        for (int nt = 0; nt < 2; nt++) {
            float p0 = __expf(s[nt][0] - mnew_lo);
            float p1 = __expf(s[nt][1] - mnew_lo);
            float p2 = __expf(s[nt][2] - mnew_hi);
            float p3 = __expf(s[nt][3] - mnew_hi);
            sumlo += p0 + p1;
            sumhi += p2 + p3;
            const int col = wn * 16 + nt * 8 + 2 * tig;
            float2 w0; w0.x = tf32_rd(p0); w0.y = tf32_rd(p1);
            float2 w1; w1.x = tf32_rd(p2); w1.y = tf32_rd(p3);
            *(float2*)&Ps[rlo * FL_PLD + col] = w0;
            *(float2*)&Ps[rhi * FL_PLD + col] = w1;
        }
#pragma unroll
        for (int off = 1; off < 4; off <<= 1) {
            sumlo += __shfl_xor_sync(0xffffffffu, sumlo, off);
            sumhi += __shfl_xor_sync(0xffffffffu, sumhi, off);
        }
        if (tig == 0) { ssum[wn * 64 + rlo] = sumlo; ssum[wn * 64 + rhi] = sumhi; }

        // rescale O
#pragma unroll
        for (int nt = 0; nt < 4; nt++) {
            o[nt][0] *= corr_lo; o[nt][1] *= corr_lo;
            o[nt][2] *= corr_hi; o[nt][3] *= corr_hi;
        }
        __syncthreads();   // (C)

        // update running stats (one thread per row)
        if (tid < 64) {
            const int r = tid;
            const float mo = rowm[r];
            const float mn = fmaxf(mo, fmaxf(smax[r], smax[64 + r]));
            const float c  = __expf(mo - mn);
            rowl[r] = rowl[r] * c + ssum[r] + ssum[64 + r];
            rowm[r] = mn;
        }

        // ---- O += P @ V  (warp tile 16 rows x 32 cols) ----
#pragma unroll
        for (int ks = 0; ks < 4; ks++) {
            const int k0 = ks * 8;
            const int a0i = rlo * FL_PLD + k0 + tig;
            const int a1i = rhi * FL_PLD + k0 + tig;
            const uint32_t a0 = __float_as_uint(Ps[a0i]);
            const uint32_t a1 = __float_as_uint(Ps[a1i]);
            const uint32_t a2 = __float_as_uint(Ps[a0i + 4]);
            const uint32_t a3 = __float_as_uint(Ps[a1i + 4]);
#pragma unroll
            for (int nt = 0; nt < 4; nt++) {
                const int nb0 = (k0 + tig)     * FL_VLD + wn * 32 + nt * 8 + g;
                const int nb1 = (k0 + tig + 4) * FL_VLD + wn * 32 + nt * 8 + g;
                const uint32_t bh0 = __float_as_uint(Vhi[nb0]);
                const uint32_t bh1 = __float_as_uint(Vhi[nb1]);
                const uint32_t bl0 = __float_as_uint(Vlo[nb0]);
                const uint32_t bl1 = __float_as_uint(Vlo[nb1]);
                MMA_TF32(o[nt], a0, a1, a2, a3, bh0, bh1);
                MMA_TF32(o[nt], a0, a1, a2, a3, bl0, bl1);
            }
        }
        __syncthreads();   // (D) all reads of K/V/Ps done
    }

    // ---- normalize + store to g_att [B,T,C] ----
    const float inv_lo = 1.f / rowl[rlo];
    const float inv_hi = 1.f / rowl[rhi];
    const int b = bh >> 4, h = bh & 15;
    const int t_lo = q0 + rlo, t_hi = q0 + rhi;
#pragma unroll
    for (int nt = 0; nt < 4; nt++) {
        const int d = wn * 32 + nt * 8 + 2 * tig;
        float2 v0; v0.x = o[nt][0] * inv_lo; v0.y = o[nt][1] * inv_lo;
        float2 v1; v1.x = o[nt][2] * inv_hi; v1.y = o[nt][3] * inv_hi;
        *(float2*)&g_att[((size_t)(b * T_ + t_lo)) * C_ + h * HD_ + d] = v0;
        *(float2*)&g_att[((size_t)(b * T_ + t_hi)) * C_ + h * HD_ + d] = v1;
    }
}

// ===========================================================================
// Launch
// ===========================================================================
extern "C" void kernel_launch(void* const* d_in, const int* in_sizes, int n_in,
                              void* d_out, int out_size)
{
    const float* x      = (const float*)d_in[0];
    const float* w_attn = (const float*)d_in[1];
    const float* b_attn = (const float*)d_in[2];
    const float* w_proj = (const float*)d_in[3];
    const float* b_proj = (const float*)d_in[4];
    float* out = (float*)d_out;

    float* wt  = nullptr;  cudaGetSymbolAddress((void**)&wt,  g_wt);
    float* wtp = nullptr;  cudaGetSymbolAddress((void**)&wtp, g_wtp);

    cudaFuncSetAttribute(flash_hmma,
                         cudaFuncAttributeMaxDynamicSharedMemorySize, FL_SMEM);

    // Transpose weights to K-major
    transpose_k<<<dim3(3072/32, 1024/32), dim3(32, 8)>>>(w_attn, wt, 1024, 3072);
    transpose_k<<<dim3(1024/32, 1024/32), dim3(32, 8)>>>(w_proj, wtp, 1024, 1024);

    // QKV GEMM: M=8192, N=3072 (HMMA tf32 3x)
    hmma_gemm<3072, true><<<dim3(3072/128, M_/128), 256>>>(x, wt, b_attn, nullptr);

    // Flash attention (HMMA)
    flash_hmma<<<dim3(T_/64, B_*NH_), 256, FL_SMEM>>>();

    // Output projection: M=8192, N=1024 (A read from g_att inside the kernel)
    hmma_gemm<1024, false><<<dim3(1024/128, M_/128), 256>>>(nullptr, wtp, b_proj, out);
}

// round 6
// speedup vs baseline: 1.7511x; 1.1515x over previous
#include <cuda_runtime.h>
#include <cuda.h>
#include <math.h>
#include <stdint.h>

#define B_   4
#define T_   2048
#define C_   1024
#define NH_  16
#define HD_  64
#define M_   (B_*T_)      // 8192

// Scratch (allocation-free: __device__ globals)
__device__ float g_q[B_*NH_*T_*HD_];
__device__ float g_k[B_*NH_*T_*HD_];
__device__ float g_v[B_*NH_*T_*HD_];
__device__ float g_att[M_*C_];
__device__ float g_wt[3*C_*C_];    // w_attn^T  [3072][1024]
__device__ float g_wtp[C_*C_];     // w_proj^T  [1024][1024]

// ===========================================================================
// Helpers
// ===========================================================================
__device__ __forceinline__ uint32_t smem_u32(const void* p) {
    uint32_t a;
    asm("{ .reg .u64 t; cvta.to.shared.u64 t, %1; cvt.u32.u64 %0, t; }" : "=r"(a) : "l"(p));
    return a;
}
__device__ __forceinline__ float tf32_rd(float x) {
    uint32_t u; asm("cvt.rna.tf32.f32 %0, %1;" : "=r"(u) : "f"(x));
    return __uint_as_float(u);
}
// in-register Dekker split
#define SPLIT(raw, hi, lo) do { \
    float _h = tf32_rd(raw); \
    hi = __float_as_uint(_h); \
    lo = __float_as_uint(tf32_rd((raw) - _h)); \
} while (0)

#define MMA_TF32(c, a0v, a1v, a2v, a3v, b0v, b1v) \
    asm volatile("mma.sync.aligned.m16n8k8.row.col.f32.tf32.tf32.f32 " \
        "{%0,%1,%2,%3}, {%4,%5,%6,%7}, {%8,%9}, {%0,%1,%2,%3};" \
        : "+f"((c)[0]), "+f"((c)[1]), "+f"((c)[2]), "+f"((c)[3]) \
        : "r"(a0v), "r"(a1v), "r"(a2v), "r"(a3v), "r"(b0v), "r"(b1v))

#define CP_ASYNC16(saddr, gptr) \
    asm volatile("cp.async.cg.shared.global [%0], [%1], 16;" :: "r"(saddr), "l"(gptr))
#define CP_COMMIT() asm volatile("cp.async.commit_group;" ::: "memory")
#define CP_WAIT(n)  asm volatile("cp.async.wait_group %0;" :: "n"(n) : "memory")

// ===========================================================================
// Transpose: out[c][r] = in[r][c]
// ===========================================================================
__global__ __launch_bounds__(256)
void transpose_k(const float* __restrict__ in, float* __restrict__ out, int R, int C)
{
    __shared__ float t[32][33];
    int x  = blockIdx.x * 32 + threadIdx.x;
    int y0 = blockIdx.y * 32 + threadIdx.y;
#pragma unroll
    for (int i = 0; i < 32; i += 8)
        t[threadIdx.y + i][threadIdx.x] = in[(size_t)(y0 + i) * C + x];
    __syncthreads();
    int x2 = blockIdx.y * 32 + threadIdx.x;
    int y2 = blockIdx.x * 32 + threadIdx.y;
#pragma unroll
    for (int i = 0; i < 32; i += 8)
        out[(size_t)(y2 + i) * R + x2] = t[threadIdx.x][threadIdx.y + i];
}

// ===========================================================================
// HMMA tf32 GEMM (3xTF32), v2: raw staging + reg split, BK=32,
// double-buffered cp.async.  Tile 128x128, 8 warps (2m x 4n).
// ===========================================================================
#define GLD 36                       // smem row stride (144 B, 16B-aligned)
#define GSTG (128*GLD)               // floats per stage per matrix
#define GEMM_SMEM_V2 (4*GSTG*4)      // 73728 B

template<int NTOT, bool QKV>
__global__ __launch_bounds__(256, 2)
void hmma_gemm(const float* __restrict__ Ain, const float* __restrict__ WT,
               const float* __restrict__ bias, float* __restrict__ out)
{
    extern __shared__ float smg[];
    float* As = smg;                 // [2][GSTG]
    float* Bs = smg + 2*GSTG;        // [2][GSTG]
    const uint32_t sA = smem_u32(As), sB = smem_u32(Bs);

    const int tid  = threadIdx.x;
    const int lane = tid & 31;
    const int wid  = tid >> 5;
    const int wm   = wid & 1;
    const int wn   = wid >> 1;
    const int m0   = blockIdx.y * 128;
    const int n0   = blockIdx.x * 128;
    const int g    = lane >> 2;
    const int tig  = lane & 3;

    const float* A  = QKV ? Ain : (const float*)g_att;
    const float* Ap = A  + (size_t)m0 * 1024;
    const float* Wp = WT + (size_t)n0 * 1024;

    float acc[4][4][4];
#pragma unroll
    for (int i = 0; i < 4; i++)
#pragma unroll
        for (int j = 0; j < 4; j++)
#pragma unroll
            for (int e = 0; e < 4; e++) acc[i][j][e] = 0.f;

    const int crow = tid >> 3;       // 0..31? no: 256 threads -> idx>>3 covers 128 rows over 4 iters
    const int cc4  = tid & 7;

    // --- pipeline ---
#pragma unroll 1
    for (int kc = -1; kc < 32; kc++) {
        // submit stage kc+1
        const int knext = kc + 1;
        if (knext < 32) {
            const int s = knext & 1;
            const uint32_t bA = sA + s * GSTG * 4;
            const uint32_t bB = sB + s * GSTG * 4;
#pragma unroll
            for (int i = 0; i < 4; i++) {
                const int row = crow + i * 32;
                const uint32_t so = (uint32_t)(row * GLD + cc4 * 4) * 4u;
                CP_ASYNC16(bA + so, Ap + (size_t)row * 1024 + knext * 32 + cc4 * 4);
                CP_ASYNC16(bB + so, Wp + (size_t)row * 1024 + knext * 32 + cc4 * 4);
            }
            CP_COMMIT();
        }
        if (kc < 0) continue;        // prologue: only submit stage 0

        if (knext < 32) CP_WAIT(1); else CP_WAIT(0);
        __syncthreads();

        const float* Asb = As + (kc & 1) * GSTG;
        const float* Bsb = Bs + (kc & 1) * GSTG;

#pragma unroll
        for (int ks = 0; ks < 4; ks++) {
            const int k0 = ks * 8;
            uint32_t ah[4][4], al[4][4];
#pragma unroll
            for (int mt = 0; mt < 4; mt++) {
                const int r  = wm * 64 + mt * 16;
                const int i0 = (r + g)     * GLD + k0 + tig;
                const int i1 = (r + 8 + g) * GLD + k0 + tig;
                const float r0 = Asb[i0], r1 = Asb[i1], r2 = Asb[i0 + 4], r3 = Asb[i1 + 4];
                SPLIT(r0, ah[mt][0], al[mt][0]);
                SPLIT(r1, ah[mt][1], al[mt][1]);
                SPLIT(r2, ah[mt][2], al[mt][2]);
                SPLIT(r3, ah[mt][3], al[mt][3]);
            }
#pragma unroll
            for (int nt = 0; nt < 4; nt++) {
                const int nb = (wn * 32 + nt * 8 + g) * GLD + k0 + tig;
                const float b0r = Bsb[nb], b1r = Bsb[nb + 4];
                uint32_t bh0, bl0, bh1, bl1;
                SPLIT(b0r, bh0, bl0);
                SPLIT(b1r, bh1, bl1);
#pragma unroll
                for (int mt = 0; mt < 4; mt++) {
                    MMA_TF32(acc[mt][nt], ah[mt][0], ah[mt][1], ah[mt][2], ah[mt][3], bh0, bh1);
                    MMA_TF32(acc[mt][nt], al[mt][0], al[mt][1], al[mt][2], al[mt][3], bh0, bh1);
                    MMA_TF32(acc[mt][nt], ah[mt][0], ah[mt][1], ah[mt][2], ah[mt][3], bl0, bl1);
                }
            }
        }
        __syncthreads();
    }

    // ---- epilogue ----
#pragma unroll
    for (int mt = 0; mt < 4; mt++) {
#pragma unroll
        for (int nt = 0; nt < 4; nt++) {
            const int n = n0 + wn * 32 + nt * 8 + tig * 2;
            const float bx = bias[n], by = bias[n + 1];
#pragma unroll
            for (int half = 0; half < 2; half++) {
                const int m = m0 + wm * 64 + mt * 16 + g + half * 8;
                float2 v;
                v.x = acc[mt][nt][half * 2 + 0] + bx;
                v.y = acc[mt][nt][half * 2 + 1] + by;
                if (QKV) {
                    const int bb = m >> 11;
                    const int tt = m & (T_ - 1);
                    const int which = n >> 10;
                    const int cc = n & (C_ - 1);
                    const int h = cc >> 6;
                    const int d = cc & (HD_ - 1);
                    float* dst = (which == 0) ? g_q : (which == 1) ? g_k : g_v;
                    *(float2*)&dst[(((size_t)(bb * NH_ + h)) * T_ + tt) * HD_ + d] = v;
                } else {
                    *(float2*)&out[(size_t)m * NTOT + n] = v;
                }
            }
        }
    }
}

// ===========================================================================
// HMMA flash attention v2: raw staging + reg split -> 45 KB smem, 4 CTAs/SM.
// BQ=64, BK=32, 8 warps (4m x 2n), register softmax.
// Float offsets: Qs 0 (64x68), Ks 4352 (32x68), Vs 6528 (32x72),
//   Ps 8832 (64x36), rowm 11136, rowl 11200, smax 11264(128), ssum 11392(128)
// ===========================================================================
#define FQ_LD 68
#define FK_LD 68
#define FV_LD 72
#define FP_LD 36
#define FL_SMEM (11520 * 4)

__global__ __launch_bounds__(256, 4)
void flash_hmma()
{
    extern __shared__ float sm[];
    float* Qs   = sm;
    float* Ks   = sm + 4352;
    float* Vs   = sm + 6528;
    float* Ps   = sm + 8832;
    float* rowm = sm + 11136;
    float* rowl = sm + 11200;
    float* smax = sm + 11264;   // [2][64]
    float* ssum = sm + 11392;   // [2][64]

    const int tid  = threadIdx.x;
    const int lane = tid & 31;
    const int wid  = tid >> 5;
    const int wm   = wid & 3;
    const int wn   = wid >> 2;
    const int g    = lane >> 2;
    const int tig  = lane & 3;

    const int qi = blockIdx.x;
    const int bh = blockIdx.y;
    const int q0 = qi * 64;

    const float* Qg = g_q + (size_t)bh * T_ * HD_ + (size_t)q0 * HD_;
    const float* Kg = g_k + (size_t)bh * T_ * HD_;
    const float* Vg = g_v + (size_t)bh * T_ * HD_;

    // load Q raw (64x64)
#pragma unroll
    for (int it = 0; it < 4; it++) {
        const int idx = tid + it * 256;
        const int r = idx >> 4, c4 = idx & 15;
        *(float4*)&Qs[r * FQ_LD + c4 * 4] = *(const float4*)(Qg + r * HD_ + c4 * 4);
    }
    if (tid < 64) { rowm[tid] = -INFINITY; rowl[tid] = 0.f; }

    const int rlo = wm * 16 + g;
    const int rhi = rlo + 8;

    float o[4][4];
#pragma unroll
    for (int nt = 0; nt < 4; nt++)
#pragma unroll
        for (int e = 0; e < 4; e++) o[nt][e] = 0.f;

    __syncthreads();

    const int nkt = 2 * qi + 2;
    for (int kt = 0; kt < nkt; kt++) {
        // load K,V raw (32x64 each)
#pragma unroll
        for (int it = 0; it < 2; it++) {
            const int idx = tid + it * 256;
            const int r = idx >> 4, c4 = idx & 15;
            *(float4*)&Ks[r * FK_LD + c4 * 4] =
                *(const float4*)(Kg + (size_t)(kt * 32 + r) * HD_ + c4 * 4);
            *(float4*)&Vs[r * FV_LD + c4 * 4] =
                *(const float4*)(Vg + (size_t)(kt * 32 + r) * HD_ + c4 * 4);
        }
        __syncthreads();   // (A)

        // ---- S = Q @ K^T (3xTF32) ----
        float s[2][4];
#pragma unroll
        for (int nt = 0; nt < 2; nt++)
#pragma unroll
            for (int e = 0; e < 4; e++) s[nt][e] = 0.f;

#pragma unroll
        for (int ks = 0; ks < 8; ks++) {
            const int k0 = ks * 8;
            const int a0i = rlo * FQ_LD + k0 + tig;
            const int a1i = rhi * FQ_LD + k0 + tig;
            const float q0r = Qs[a0i], q1r = Qs[a1i], q2r = Qs[a0i + 4], q3r = Qs[a1i + 4];
            uint32_t ah0, al0, ah1, al1, ah2, al2, ah3, al3;
            SPLIT(q0r, ah0, al0); SPLIT(q1r, ah1, al1);
            SPLIT(q2r, ah2, al2); SPLIT(q3r, ah3, al3);
#pragma unroll
            for (int nt = 0; nt < 2; nt++) {
                const int nb = (wn * 16 + nt * 8 + g) * FK_LD + k0 + tig;
                const float k0r = Ks[nb], k1r = Ks[nb + 4];
                uint32_t bh0, bl0, bh1, bl1;
                SPLIT(k0r, bh0, bl0); SPLIT(k1r, bh1, bl1);
                MMA_TF32(s[nt], ah0, ah1, ah2, ah3, bh0, bh1);
                MMA_TF32(s[nt], al0, al1, al2, al3, bh0, bh1);
                MMA_TF32(s[nt], ah0, ah1, ah2, ah3, bl0, bl1);
            }
        }

        // ---- scale + causal mask + row max ----
        const int qrow_lo = q0 + rlo;
        const int qrow_hi = q0 + rhi;
        float mlo = -INFINITY, mhi = -INFINITY;
#pragma unroll
        for (int nt = 0; nt < 2; nt++) {
            const int colb = kt * 32 + wn * 16 + nt * 8 + 2 * tig;
#pragma unroll
            for (int j = 0; j < 2; j++) {
                float v0 = s[nt][j] * 0.125f;
                if (colb + j > qrow_lo) v0 = -INFINITY;
                s[nt][j] = v0;
                mlo = fmaxf(mlo, v0);
                float v1 = s[nt][2 + j] * 0.125f;
                if (colb + j > qrow_hi) v1 = -INFINITY;
                s[nt][2 + j] = v1;
                mhi = fmaxf(mhi, v1);
            }
        }
#pragma unroll
        for (int off = 1; off < 4; off <<= 1) {
            mlo = fmaxf(mlo, __shfl_xor_sync(0xffffffffu, mlo, off));
            mhi = fmaxf(mhi, __shfl_xor_sync(0xffffffffu, mhi, off));
        }
        if (tig == 0) { smax[wn * 64 + rlo] = mlo; smax[wn * 64 + rhi] = mhi; }
        __syncthreads();   // (B)

        // ---- combine stats, exp, write P ----
        const float mold_lo = rowm[rlo];
        const float mold_hi = rowm[rhi];
        const float mnew_lo = fmaxf(mold_lo, fmaxf(smax[rlo], smax[64 + rlo]));
        const float mnew_hi = fmaxf(mold_hi, fmaxf(smax[rhi], smax[64 + rhi]));
        const float corr_lo = __expf(mold_lo - mnew_lo);
        const float corr_hi = __expf(mold_hi - mnew_hi);

        float sumlo = 0.f, sumhi = 0.f;
#pragma unroll
        for (int nt = 0; nt < 2; nt++) {
            float p0 = __expf(s[nt][0] - mnew_lo);
            float p1 = __expf(s[nt][1] - mnew_lo);
            float p2 = __expf(s[nt][2] - mnew_hi);
            float p3 = __expf(s[nt][3] - mnew_hi);
            sumlo += p0 + p1;
            sumhi += p2 + p3;
            const int col = wn * 16 + nt * 8 + 2 * tig;
            float2 w0; w0.x = tf32_rd(p0); w0.y = tf32_rd(p1);
            float2 w1; w1.x = tf32_rd(p2); w1.y = tf32_rd(p3);
            *(float2*)&Ps[rlo * FP_LD + col] = w0;
            *(float2*)&Ps[rhi * FP_LD + col] = w1;
        }
#pragma unroll
        for (int off = 1; off < 4; off <<= 1) {
            sumlo += __shfl_xor_sync(0xffffffffu, sumlo, off);
            sumhi += __shfl_xor_sync(0xffffffffu, sumhi, off);
        }
        if (tig == 0) { ssum[wn * 64 + rlo] = sumlo; ssum[wn * 64 + rhi] = sumhi; }

        // rescale O
#pragma unroll
        for (int nt = 0; nt < 4; nt++) {
            o[nt][0] *= corr_lo; o[nt][1] *= corr_lo;
            o[nt][2] *= corr_hi; o[nt][3] *= corr_hi;
        }
        __syncthreads();   // (C)

        if (tid < 64) {
            const int r = tid;
            const float mo = rowm[r];
            const float mn = fmaxf(mo, fmaxf(smax[r], smax[64 + r]));
            const float c  = __expf(mo - mn);
            rowl[r] = rowl[r] * c + ssum[r] + ssum[64 + r];
            rowm[r] = mn;
        }

        // ---- O += P @ V ----
#pragma unroll
        for (int ks = 0; ks < 4; ks++) {
            const int k0 = ks * 8;
            const int a0i = rlo * FP_LD + k0 + tig;
            const int a1i = rhi * FP_LD + k0 + tig;
            const uint32_t a0 = __float_as_uint(Ps[a0i]);
            const uint32_t a1 = __float_as_uint(Ps[a1i]);
            const uint32_t a2 = __float_as_uint(Ps[a0i + 4]);
            const uint32_t a3 = __float_as_uint(Ps[a1i + 4]);
#pragma unroll
            for (int nt = 0; nt < 4; nt++) {
                const int nb0 = (k0 + tig)     * FV_LD + wn * 32 + nt * 8 + g;
                const int nb1 = (k0 + tig + 4) * FV_LD + wn * 32 + nt * 8 + g;
                const float v0r = Vs[nb0], v1r = Vs[nb1];
                uint32_t vh0, vl0, vh1, vl1;
                SPLIT(v0r, vh0, vl0); SPLIT(v1r, vh1, vl1);
                MMA_TF32(o[nt], a0, a1, a2, a3, vh0, vh1);
                MMA_TF32(o[nt], a0, a1, a2, a3, vl0, vl1);
            }
        }
        __syncthreads();   // (D)
    }

    // ---- normalize + store ----
    const float inv_lo = 1.f / rowl[rlo];
    const float inv_hi = 1.f / rowl[rhi];
    const int b = bh >> 4, h = bh & 15;
    const int t_lo = q0 + rlo, t_hi = q0 + rhi;
#pragma unroll
    for (int nt = 0; nt < 4; nt++) {
        const int d = wn * 32 + nt * 8 + 2 * tig;
        float2 v0; v0.x = o[nt][0] * inv_lo; v0.y = o[nt][1] * inv_lo;
        float2 v1; v1.x = o[nt][2] * inv_hi; v1.y = o[nt][3] * inv_hi;
        *(float2*)&g_att[((size_t)(b * T_ + t_lo)) * C_ + h * HD_ + d] = v0;
        *(float2*)&g_att[((size_t)(b * T_ + t_hi)) * C_ + h * HD_ + d] = v1;
    }
}

// ===========================================================================
// Launch
// ===========================================================================
extern "C" void kernel_launch(void* const* d_in, const int* in_sizes, int n_in,
                              void* d_out, int out_size)
{
    const float* x      = (const float*)d_in[0];
    const float* w_attn = (const float*)d_in[1];
    const float* b_attn = (const float*)d_in[2];
    const float* w_proj = (const float*)d_in[3];
    const float* b_proj = (const float*)d_in[4];
    float* out = (float*)d_out;

    float* wt  = nullptr;  cudaGetSymbolAddress((void**)&wt,  g_wt);
    float* wtp = nullptr;  cudaGetSymbolAddress((void**)&wtp, g_wtp);

    cudaFuncSetAttribute(flash_hmma,
                         cudaFuncAttributeMaxDynamicSharedMemorySize, FL_SMEM);
    cudaFuncSetAttribute(hmma_gemm<3072, true>,
                         cudaFuncAttributeMaxDynamicSharedMemorySize, GEMM_SMEM_V2);
    cudaFuncSetAttribute(hmma_gemm<1024, false>,
                         cudaFuncAttributeMaxDynamicSharedMemorySize, GEMM_SMEM_V2);

    // Transpose weights to K-major
    transpose_k<<<dim3(3072/32, 1024/32), dim3(32, 8)>>>(w_attn, wt, 1024, 3072);
    transpose_k<<<dim3(1024/32, 1024/32), dim3(32, 8)>>>(w_proj, wtp, 1024, 1024);

    // QKV GEMM: M=8192, N=3072
    hmma_gemm<3072, true><<<dim3(3072/128, M_/128), 256, GEMM_SMEM_V2>>>(x, wt, b_attn, nullptr);

    // Flash attention
    flash_hmma<<<dim3(T_/64, B_*NH_), 256, FL_SMEM>>>();

    // Output projection: M=8192, N=1024
    hmma_gemm<1024, false><<<dim3(1024/128, M_/128), 256, GEMM_SMEM_V2>>>(nullptr, wtp, b_proj, out);
}